// round 11
// baseline (speedup 1.0000x reference)
#include <cuda_runtime.h>
#include <cuda_fp16.h>
#include <cstdint>
#include <math.h>

#define TOK 32768
#define HDIM 1152
#define LHD 1152
#define HHD 4608
#define NCAT 5760          // LHD + HHD
#define BM 128
#define BN 128
#define BK 64
#define STAGES 3
#define RB (TOK / 8)

// ---------------- device scratch (allocation-free rule) ----------------
__device__ float  d_probs[TOK * 2];
__device__ float  d_b1cat[NCAT];
__device__ __half d_xh[(size_t)TOK * HDIM];
__device__ __half d_cat[(size_t)TOK * NCAT];      // [p0*gelu(fc1l) | p1*gelu(fc1h)]
__device__ __half d_w1cat[(size_t)NCAT * HDIM];   // [w1l ; w1h] row-concat
__device__ __half d_w2cat[(size_t)HDIM * NCAT];   // per-row k-concat [w2l | w2h]

// ---------------- helpers ----------------
__device__ __forceinline__ float gelu_ref(float v) {
    return 0.5f * v * (1.0f + erff(v * 0.70710678118654752f));
}
__device__ __forceinline__ void cpa16(uint32_t saddr, const void* gaddr) {
    asm volatile("cp.async.cg.shared.global [%0], [%1], 16;" :: "r"(saddr), "l"(gaddr));
}
__device__ __forceinline__ uint32_t to_smem(const void* p) {
    uint32_t a;
    asm("{ .reg .u64 t; cvta.to.shared.u64 t, %1; cvt.u32.u64 %0, t; }" : "=r"(a) : "l"(p));
    return a;
}
#define SWZ(o) ((o) ^ (((o) >> 3) & 0x70))

__device__ __forceinline__ void ldsm4(uint32_t& r0, uint32_t& r1, uint32_t& r2, uint32_t& r3,
                                      uint32_t saddr) {
    asm volatile("ldmatrix.sync.aligned.m8n8.x4.shared.b16 {%0,%1,%2,%3}, [%4];"
                 : "=r"(r0), "=r"(r1), "=r"(r2), "=r"(r3) : "r"(saddr));
}
__device__ __forceinline__ void hmma(float* d, const uint32_t* a, uint32_t b0, uint32_t b1) {
    asm volatile(
        "mma.sync.aligned.m16n8k16.row.col.f32.f16.f16.f32 "
        "{%0,%1,%2,%3}, {%4,%5,%6,%7}, {%8,%9}, {%0,%1,%2,%3};"
        : "+f"(d[0]), "+f"(d[1]), "+f"(d[2]), "+f"(d[3])
        : "r"(a[0]), "r"(a[1]), "r"(a[2]), "r"(a[3]), "r"(b0), "r"(b1));
}

// ---------------------------------------------------------------------------
// Fused prep + router kernel.
// blocks [0, RB): router (warp/token) + fp16 x;  blocks [RB,..): weight prep.
// ---------------------------------------------------------------------------
__global__ void fused_prep(
    const float* __restrict__ x, const float* __restrict__ rw, const float* __restrict__ rb,
    const float* __restrict__ lw1, const float* __restrict__ hw1,
    const float* __restrict__ lw2, const float* __restrict__ hw2,
    const float* __restrict__ lb1, const float* __restrict__ hb1,
    float* __restrict__ probs, __half* __restrict__ xh,
    __half* __restrict__ w1cat, __half* __restrict__ w2cat, float* __restrict__ b1cat) {
    const int bx = blockIdx.x;
    if (bx < RB) {
        const int t = bx * 8 + (threadIdx.x >> 5);
        const int lane = threadIdx.x & 31;
        const float* xt = x + (size_t)t * HDIM;
        __half* xht = xh + (size_t)t * HDIM;
        float l0 = 0.f, l1 = 0.f;
        #pragma unroll 4
        for (int i = lane; i < HDIM; i += 32) {
            const float v = xt[i];
            xht[i] = __float2half_rn(v);
            l0 += v * rw[i];
            l1 += v * rw[HDIM + i];
        }
        #pragma unroll
        for (int o = 16; o; o >>= 1) {
            l0 += __shfl_xor_sync(0xFFFFFFFFu, l0, o);
            l1 += __shfl_xor_sync(0xFFFFFFFFu, l1, o);
        }
        if (lane == 0) {
            l0 += rb[0];
            l1 += rb[1];
            const float m = fmaxf(l0, l1);
            const float e0 = expf(l0 - m), e1 = expf(l1 - m);
            const float s = 1.0f / (e0 + e1);
            probs[t * 2 + 0] = e0 * s;
            probs[t * 2 + 1] = e1 * s;
        }
        return;
    }
    const int n1 = LHD * HDIM / 4;
    const int n2 = HHD * HDIM / 4;
    const int n3 = HDIM * NCAT / 4;
    const int nb = NCAT / 4;
    const int i = (bx - RB) * 256 + threadIdx.x;
    if (i >= n1 + n2 + n3 + nb) return;
    if (i < n1) {
        const float4 v = ((const float4*)lw1)[i];
        ((__half2*)w1cat)[i * 2 + 0] = __floats2half2_rn(v.x, v.y);
        ((__half2*)w1cat)[i * 2 + 1] = __floats2half2_rn(v.z, v.w);
    } else if (i < n1 + n2) {
        const int j = i - n1;
        const float4 v = ((const float4*)hw1)[j];
        __half2* dst = (__half2*)(w1cat + (size_t)LHD * HDIM);
        dst[j * 2 + 0] = __floats2half2_rn(v.x, v.y);
        dst[j * 2 + 1] = __floats2half2_rn(v.z, v.w);
    } else if (i < n1 + n2 + n3) {
        const int j = i - n1 - n2;
        const int e = j * 4;
        const int r = e / NCAT, k = e % NCAT;
        float4 v;
        if (k < LHD) v = *(const float4*)(lw2 + (size_t)r * LHD + k);
        else         v = *(const float4*)(hw2 + (size_t)r * HHD + (k - LHD));
        ((__half2*)w2cat)[j * 2 + 0] = __floats2half2_rn(v.x, v.y);
        ((__half2*)w2cat)[j * 2 + 1] = __floats2half2_rn(v.z, v.w);
    } else {
        const int j = (i - n1 - n2 - n3) * 4;
        #pragma unroll
        for (int q = 0; q < 4; q++) {
            const int k = j + q;
            b1cat[k] = (k < LHD) ? lb1[k] : hb1[k - LHD];
        }
    }
}

// ---------------------------------------------------------------------------
// fp16 GEMM: 128x128x64 CTA, 4 warps (2x2), warp tile 64x64, 3-stage cp.async,
// single __syncthreads per K-tile, 2 CTAs/SM. N/K compile-time constants;
// LDSM addresses precomputed once with ks folded in as pure XOR under SW128.
//   MODE 0 (fc1 fused): C(half) = p[row, expert(col)] * gelu(acc + b1cat[col])
//   MODE 1 (fc2 fused): C(float) = acc + p0[row]*lb2[col] + p1[row]*hb2[col]
// ---------------------------------------------------------------------------
template <int MODE, int NN, int KK>
__global__ void __launch_bounds__(128, 2)
gemm_core(const __half* __restrict__ A, const __half* __restrict__ B,
          const float* __restrict__ biasA, const float* __restrict__ biasB,
          const float* __restrict__ probs, void* __restrict__ Cv) {
    constexpr int TILE = BM * BK * 2;       // 16384 B per matrix
    constexpr int STAGE = 2 * TILE;         // 32768 B
    constexpr int KT = KK / BK;
    extern __shared__ char smem_raw[];
    const uint32_t S0 = to_smem(smem_raw);
    float* sBias = (float*)(smem_raw + STAGES * STAGE);

    const int tid = threadIdx.x;
    const int warp = tid >> 5;
    const int lane = tid & 31;
    const int g = lane >> 2, tg = lane & 3;
    const int wm = (warp >> 1) * 64;
    const int wn = (warp & 1) * 64;
    const int mBase = blockIdx.y * BM, nBase = blockIdx.x * BN;

    if (tid < BN) {
        sBias[tid] = biasA[nBase + tid];
        if (MODE == 1) sBias[BN + tid] = biasB[nBase + tid];
    }

    // precomputed cp.async mapping (fixed per thread)
    const int crow = tid >> 3;
    const int ccol = tid & 7;
    const __half* srcA = A + (size_t)(mBase + crow) * KK + ccol * 8;
    const __half* srcB = B + (size_t)(nBase + crow) * KK + ccol * 8;
    const uint32_t dst0 = SWZ(crow * 128 + ccol * 16);

    auto issue = [&](int kt) {
        const uint32_t pA = S0 + (kt % STAGES) * STAGE + dst0;
        const uint32_t pB = pA + TILE;
        const int k0 = kt * BK;
        #pragma unroll
        for (int it = 0; it < 8; it++)
            cpa16(pA + it * 2048, srcA + k0 + it * (size_t)(16 * KK));
        #pragma unroll
        for (int it = 0; it < 8; it++)
            cpa16(pB + it * 2048, srcB + k0 + it * (size_t)(16 * KK));
        asm volatile("cp.async.commit_group;");
    };

    float acc[4][8][4];
    #pragma unroll
    for (int mi = 0; mi < 4; mi++)
        #pragma unroll
        for (int ni = 0; ni < 8; ni++)
            #pragma unroll
            for (int j = 0; j < 4; j++) acc[mi][ni][j] = 0.f;

    issue(0); issue(1);

    // precomputed LDSM base addresses; kb (bits 5-6) applies as pure XOR
    const int lmr = lane & 15;
    const int lmk = (lane >> 4) * 16;
    uint32_t aB[4], bB[4];
    #pragma unroll
    for (int mi = 0; mi < 4; mi++)
        aB[mi] = SWZ((wm + mi * 16 + lmr) * 128 + lmk);
    #pragma unroll
    for (int np = 0; np < 4; np++)
        bB[np] = (uint32_t)TILE + SWZ((wn + np * 16 + lmr) * 128 + lmk);

    for (int kt = 0; kt < KT; kt++) {
        if (kt + 1 < KT) asm volatile("cp.async.wait_group 1;");
        else             asm volatile("cp.async.wait_group 0;");
        __syncthreads();
        if (kt + 2 < KT) issue(kt + 2);

        const uint32_t stS = S0 + (kt % STAGES) * STAGE;
        uint32_t aS[4], bS[4];
        #pragma unroll
        for (int q = 0; q < 4; q++) { aS[q] = stS + aB[q]; bS[q] = stS + bB[q]; }

        #pragma unroll
        for (int ks = 0; ks < 4; ks++) {
            const uint32_t kb = ks * 32;
            uint32_t af[4][4], bf[4][4];
            #pragma unroll
            for (int mi = 0; mi < 4; mi++)
                ldsm4(af[mi][0], af[mi][1], af[mi][2], af[mi][3], aS[mi] ^ kb);
            #pragma unroll
            for (int np = 0; np < 4; np++)
                ldsm4(bf[np][0], bf[np][1], bf[np][2], bf[np][3], bS[np] ^ kb);
            #pragma unroll
            for (int mi = 0; mi < 4; mi++) {
                #pragma unroll
                for (int np = 0; np < 4; np++) {
                    hmma(acc[mi][np * 2 + 0], af[mi], bf[np][0], bf[np][2]);
                    hmma(acc[mi][np * 2 + 1], af[mi], bf[np][1], bf[np][3]);
                }
            }
        }
    }

    // -------- epilogue --------
    if (MODE == 0) {
        const int pidx = (nBase >= LHD) ? 1 : 0;
        __half* Ch = (__half*)Cv;
        #pragma unroll
        for (int mi = 0; mi < 4; mi++) {
            const int row = mBase + wm + mi * 16 + g;
            const float pa = probs[row * 2 + pidx];
            const float pb = probs[(row + 8) * 2 + pidx];
            #pragma unroll
            for (int ni = 0; ni < 8; ni++) {
                const int col = wn + ni * 8 + tg * 2;
                const float b0 = sBias[col], b1 = sBias[col + 1];
                const float v00 = acc[mi][ni][0] + b0;
                const float v01 = acc[mi][ni][1] + b1;
                const float v10 = acc[mi][ni][2] + b0;
                const float v11 = acc[mi][ni][3] + b1;
                *(__half2*)(Ch + (size_t)row * NN + nBase + col) =
                    __floats2half2_rn(pa * gelu_ref(v00), pa * gelu_ref(v01));
                *(__half2*)(Ch + (size_t)(row + 8) * NN + nBase + col) =
                    __floats2half2_rn(pb * gelu_ref(v10), pb * gelu_ref(v11));
            }
        }
    } else {
        float* Cf = (float*)Cv;
        #pragma unroll
        for (int mi = 0; mi < 4; mi++) {
            const int row = mBase + wm + mi * 16 + g;
            const float2 pr0 = ((const float2*)probs)[row];
            const float2 pr1 = ((const float2*)probs)[row + 8];
            #pragma unroll
            for (int ni = 0; ni < 8; ni++) {
                const int col = wn + ni * 8 + tg * 2;
                const float bl0 = sBias[col], bl1 = sBias[col + 1];
                const float bh0 = sBias[BN + col], bh1 = sBias[BN + col + 1];
                float2 o0, o1;
                o0.x = acc[mi][ni][0] + pr0.x * bl0 + pr0.y * bh0;
                o0.y = acc[mi][ni][1] + pr0.x * bl1 + pr0.y * bh1;
                o1.x = acc[mi][ni][2] + pr1.x * bl0 + pr1.y * bh0;
                o1.y = acc[mi][ni][3] + pr1.x * bl1 + pr1.y * bh1;
                *(float2*)(Cf + (size_t)row * NN + nBase + col) = o0;
                *(float2*)(Cf + (size_t)(row + 8) * NN + nBase + col) = o1;
            }
        }
    }
}

// ---------------------------------------------------------------------------
extern "C" void kernel_launch(void* const* d_in, const int* in_sizes, int n_in,
                              void* d_out, int out_size) {
    const float* x   = (const float*)d_in[0];
    const float* rw  = (const float*)d_in[1];
    const float* rb  = (const float*)d_in[2];
    const float* lw1 = (const float*)d_in[3];
    const float* lb1 = (const float*)d_in[4];
    const float* lw2 = (const float*)d_in[5];
    const float* lb2 = (const float*)d_in[6];
    const float* hw1 = (const float*)d_in[7];
    const float* hb1 = (const float*)d_in[8];
    const float* hw2 = (const float*)d_in[9];
    const float* hb2 = (const float*)d_in[10];
    float* out = (float*)d_out;

    __half *xh, *cat, *w1cat, *w2cat;
    float *probs, *b1cat;
    cudaGetSymbolAddress((void**)&xh, d_xh);
    cudaGetSymbolAddress((void**)&cat, d_cat);
    cudaGetSymbolAddress((void**)&probs, d_probs);
    cudaGetSymbolAddress((void**)&w1cat, d_w1cat);
    cudaGetSymbolAddress((void**)&w2cat, d_w2cat);
    cudaGetSymbolAddress((void**)&b1cat, d_b1cat);

    const int SMEM = STAGES * 2 * BM * BK * 2 + 1024;  // 99328 B
    cudaFuncSetAttribute((const void*)gemm_core<0, NCAT, HDIM>, cudaFuncAttributeMaxDynamicSharedMemorySize, SMEM);
    cudaFuncSetAttribute((const void*)gemm_core<1, HDIM, NCAT>, cudaFuncAttributeMaxDynamicSharedMemorySize, SMEM);

    // fused prep + router (one launch)
    const int n1 = LHD * HDIM / 4, n2 = HHD * HDIM / 4, n3 = HDIM * NCAT / 4, nb = NCAT / 4;
    const int prepBlocks = (n1 + n2 + n3 + nb + 255) / 256;
    fused_prep<<<RB + prepBlocks, 256>>>(
        x, rw, rb, lw1, hw1, lw2, hw2, lb1, hb1, probs, xh, w1cat, w2cat, b1cat);

    // fc1 fused: cat = p[.,expert] * gelu(xh @ w1cat^T + b1cat)   [M=32768, N=5760, K=1152]
    gemm_core<0, NCAT, HDIM><<<dim3(NCAT / BN, TOK / BM), 128, SMEM>>>(
        xh, w1cat, b1cat, nullptr, probs, cat);
    // fc2 fused: out = cat @ w2cat^T + p0*lb2 + p1*hb2            [M=32768, N=1152, K=5760]
    gemm_core<1, HDIM, NCAT><<<dim3(HDIM / BN, TOK / BM), 128, SMEM>>>(
        cat, w2cat, lb2, hb2, probs, out);
}